// round 1
// baseline (speedup 1.0000x reference)
#include <cuda_runtime.h>

#define HW 50176
#define W_ 224
#define H_ 224

// Per-image gray means, written by reduce_kernel, read by main_kernel.
__device__ float g_gm[1024];

// ---------------------------------------------------------------------------
// Kernel 1: per-image weighted reduction producing gm[b].
// gm = (1/HW) * [ sum_q coef(q) * (gw0*std0*x0 + gw1*std1*x1 + gw2*std2*x2)
//               + (gw0*m0+gw1*m1+gw2*m2) * SUM_COEF ]
// coef(q) = 0.64 + 0.36 * (ny*nx + 4)/13, ny/nx = 2 at image border else 3.
// ---------------------------------------------------------------------------
__global__ void __launch_bounds__(1024)
reduce_kernel(const float* __restrict__ x,
              const float* __restrict__ mean,
              const float* __restrict__ stdv) {
    const int b = blockIdx.x;
    const float* p = x + (size_t)b * 3 * HW;

    const float gw0 = 0.299f * stdv[0];
    const float gw1 = 0.587f * stdv[1];
    const float gw2 = 0.114f * stdv[2];

    float s = 0.f;
    for (int i = threadIdx.x; i < HW / 4; i += blockDim.x) {
        const int pix = i * 4;
        const int r = pix / W_;
        const int c0 = pix - r * W_;
        float4 a0 = *(const float4*)(p + pix);
        float4 a1 = *(const float4*)(p + HW + pix);
        float4 a2 = *(const float4*)(p + 2 * HW + pix);
        const float ny = (r == 0 || r == H_ - 1) ? 2.f : 3.f;

        float e0[4] = {a0.x, a0.y, a0.z, a0.w};
        float e1[4] = {a1.x, a1.y, a1.z, a1.w};
        float e2[4] = {a2.x, a2.y, a2.z, a2.w};
#pragma unroll
        for (int j = 0; j < 4; j++) {
            const int c = c0 + j;
            const float nx = (c == 0 || c == W_ - 1) ? 2.f : 3.f;
            const float coef = 0.64f + 0.36f * (ny * nx + 4.f) * (1.f / 13.f);
            const float gx = gw0 * e0[j] + gw1 * e1[j] + gw2 * e2[j];
            s += coef * gx;
        }
    }

    // block reduction (1024 threads = 32 warps)
    __shared__ float red[32];
#pragma unroll
    for (int off = 16; off > 0; off >>= 1)
        s += __shfl_down_sync(0xffffffffu, s, off);
    const int lane = threadIdx.x & 31;
    const int warp = threadIdx.x >> 5;
    if (lane == 0) red[warp] = s;
    __syncthreads();
    if (warp == 0) {
        s = red[lane];
#pragma unroll
        for (int off = 16; off > 0; off >>= 1)
            s += __shfl_down_sync(0xffffffffu, s, off);
        if (lane == 0) {
            // SUM_COEF = 0.64*HW + 0.36 * (sum(ny*nx) + 4*HW)/13
            // sum(ny)=sum(nx)=2*2+222*3=670 -> sum(ny*nx)=670*670=448900
            const double SC = 0.64 * (double)HW + 0.36 * (448900.0 + 4.0 * HW) / 13.0;
            const float cm = 0.299f * mean[0] + 0.587f * mean[1] + 0.114f * mean[2];
            g_gm[b] = (s + cm * (float)SC) * (1.0f / (float)HW);
        }
    }
}

// ---------------------------------------------------------------------------
// Kernel 2: fully fused per-plane pipeline.
// Each thread produces a float4 of outputs in one row of one (image,channel)
// plane. Needs a 3x6 stencil of y = x*std+mean (zero-padded), served by
// coalesced float4 loads + two cached scalar halo loads per row.
// ---------------------------------------------------------------------------
__global__ void __launch_bounds__(224)
main_kernel(const float* __restrict__ x,
            const float* __restrict__ mean,
            const float* __restrict__ stdv,
            float* __restrict__ out) {
    const int plane = blockIdx.x;             // b*3 + ch
    const int b = plane / 3;
    const int ch = plane - b * 3;
    const int r = blockIdx.y * 4 + threadIdx.y;
    const int c4 = threadIdx.x * 4;

    const float* p = x + (size_t)plane * HW;
    const float m = mean[ch];
    const float sd = stdv[ch];
    const float gm = g_gm[b];

    float yv[3][6];
#pragma unroll
    for (int dr = 0; dr < 3; dr++) {
        const int rr = r - 1 + dr;
        if (rr < 0 || rr >= H_) {
#pragma unroll
            for (int j = 0; j < 6; j++) yv[dr][j] = 0.f;
        } else {
            const float* rp = p + rr * W_ + c4;
            float4 v = *(const float4*)rp;
            yv[dr][1] = fmaf(v.x, sd, m);
            yv[dr][2] = fmaf(v.y, sd, m);
            yv[dr][3] = fmaf(v.z, sd, m);
            yv[dr][4] = fmaf(v.w, sd, m);
            yv[dr][0] = (c4 > 0)        ? fmaf(rp[-1], sd, m) : 0.f;
            yv[dr][5] = (c4 + 4 < W_)   ? fmaf(rp[4],  sd, m) : 0.f;
        }
    }

    const float k1 = 1.0f / 13.0f;
    const float k5 = 5.0f / 13.0f;
    float4 o;
    float* op = (float*)&o;
#pragma unroll
    for (int j = 0; j < 4; j++) {
        const float cen = yv[1][j + 1];
        const float ring = yv[0][j] + yv[0][j + 1] + yv[0][j + 2]
                         + yv[1][j]                + yv[1][j + 2]
                         + yv[2][j] + yv[2][j + 1] + yv[2][j + 2];
        const float blur = ring * k1 + cen * k5;
        const float y1 = 0.64f * cen + 0.36f * blur;       // blur blend
        const float y2 = (0.64f * y1 + 0.36f * gm) * 0.64f; // gm blend + scale
        const float z = (y2 < 0.3f) ? y2 : 1.0f - y2;       // solarize
        op[j] = (z - m) / sd;                               // renormalize
    }
    *(float4*)(out + (size_t)plane * HW + r * W_ + c4) = o;
}

extern "C" void kernel_launch(void* const* d_in, const int* in_sizes, int n_in,
                              void* d_out, int out_size) {
    const float* x    = (const float*)d_in[0];
    const float* mean = (const float*)d_in[1];
    const float* stdv = (const float*)d_in[2];
    float* out = (float*)d_out;

    const int B = in_sizes[0] / (3 * HW);

    reduce_kernel<<<B, 1024>>>(x, mean, stdv);

    dim3 bd(56, 4);
    dim3 gd(B * 3, H_ / 4);
    main_kernel<<<gd, bd>>>(x, mean, stdv, out);
}

// round 2
// speedup vs baseline: 1.1216x; 1.1216x over previous
#include <cuda_runtime.h>

#define HW 50176
#define W_ 224
#define H_ 224
#define SEGS 8
#define SEG_ROWS 28          // 224 / 8
#define TILE_R 16            // output rows per main block
#define IN_R   18            // input rows (TILE_R + 2 halo)

// Per-image partial weighted gray sums: g_part[b*SEGS + s]
__device__ float g_part[1024 * SEGS];

// ---------------------------------------------------------------------------
// Kernel 1: balanced partial reduction. 8 segments per image, 256 threads.
// partial = sum over segment pixels of coef(p) * (gw0*x0 + gw1*x1 + gw2*x2)
// coef(p) = 0.64 + 0.36*(ny*nx+4)/13
// ---------------------------------------------------------------------------
__global__ void __launch_bounds__(256)
reduce_kernel(const float* __restrict__ x,
              const float* __restrict__ stdv) {
    const int b = blockIdx.x >> 3;
    const int s = blockIdx.x & 7;
    const float* p = x + (size_t)b * 3 * HW + s * SEG_ROWS * W_;

    const float gw0 = 0.299f * stdv[0];
    const float gw1 = 0.587f * stdv[1];
    const float gw2 = 0.114f * stdv[2];

    float acc = 0.f;
    // SEG_ROWS*W_/4 = 1568 quads
    for (int i = threadIdx.x; i < SEG_ROWS * W_ / 4; i += 256) {
        const int pix = i * 4;
        const int lr = pix / W_;
        const int c0 = pix - lr * W_;
        const int gr = s * SEG_ROWS + lr;
        float4 a0 = *(const float4*)(p + pix);
        float4 a1 = *(const float4*)(p + HW + pix);
        float4 a2 = *(const float4*)(p + 2 * HW + pix);
        const float ny = (gr == 0 || gr == H_ - 1) ? 2.f : 3.f;

        float e0[4] = {a0.x, a0.y, a0.z, a0.w};
        float e1[4] = {a1.x, a1.y, a1.z, a1.w};
        float e2[4] = {a2.x, a2.y, a2.z, a2.w};
#pragma unroll
        for (int j = 0; j < 4; j++) {
            const int c = c0 + j;
            const float nx = (c == 0 || c == W_ - 1) ? 2.f : 3.f;
            const float coef = 0.64f + 0.36f * (ny * nx + 4.f) * (1.f / 13.f);
            const float gx = gw0 * e0[j] + gw1 * e1[j] + gw2 * e2[j];
            acc += coef * gx;
        }
    }

    __shared__ float red[8];
#pragma unroll
    for (int off = 16; off > 0; off >>= 1)
        acc += __shfl_down_sync(0xffffffffu, acc, off);
    const int lane = threadIdx.x & 31;
    const int warp = threadIdx.x >> 5;
    if (lane == 0) red[warp] = acc;
    __syncthreads();
    if (threadIdx.x == 0) {
        float t = 0.f;
#pragma unroll
        for (int w = 0; w < 8; w++) t += red[w];
        g_part[blockIdx.x] = t;
    }
}

// ---------------------------------------------------------------------------
// Kernel 2: smem-tiled fused pipeline. One block = 16 output rows of one
// (image,channel) plane. 18 input rows loaded as a flat aligned float4 copy
// with the affine y = x*std+mean applied in-flight (zeros stay zero = correct
// y-space padding). Stencil + blends + solarize + renorm from smem.
// ---------------------------------------------------------------------------
__global__ void __launch_bounds__(256)
main_kernel(const float* __restrict__ x,
            const float* __restrict__ mean,
            const float* __restrict__ stdv,
            float* __restrict__ out) {
    __shared__ float tile[IN_R * W_];        // 16128 B

    const int tiles_per_plane = H_ / TILE_R; // 14
    const int plane = blockIdx.x / tiles_per_plane;
    const int tr = blockIdx.x - plane * tiles_per_plane;
    const int b = plane / 3;
    const int ch = plane - b * 3;

    const float m = mean[ch];
    const float sd = stdv[ch];

    // gm = (sum of 8 partials + cm*SUM_COEF) / HW
    float gm;
    {
        float ps = 0.f;
#pragma unroll
        for (int i = 0; i < SEGS; i++) ps += g_part[b * SEGS + i];
        // SUM_COEF = 0.64*HW + 0.36*(448900 + 4*HW)/13  (exact, see R1)
        const double SC = 0.64 * (double)HW + 0.36 * (448900.0 + 4.0 * HW) / 13.0;
        const float cm = 0.299f * mean[0] + 0.587f * mean[1] + 0.114f * mean[2];
        gm = (ps + cm * (float)SC) * (1.0f / (float)HW);
    }

    // ---- load 18 rows (flat contiguous region), apply affine, zero-pad ----
    const float* p = x + (size_t)plane * HW;
    const int off0 = (tr * TILE_R - 1) * W_;        // float offset of smem[0]
    for (int i = threadIdx.x; i < IN_R * W_ / 4; i += 256) {
        const int off = off0 + i * 4;
        float4 v = make_float4(0.f, 0.f, 0.f, 0.f);
        if (off >= 0 && off < HW) {
            float4 u = *(const float4*)(p + off);
            v.x = fmaf(u.x, sd, m);
            v.y = fmaf(u.y, sd, m);
            v.z = fmaf(u.z, sd, m);
            v.w = fmaf(u.w, sd, m);
        }
        *(float4*)(tile + i * 4) = v;
    }
    __syncthreads();

    // ---- compute: 16 rows * 56 quads = 896 output float4 per block ----
    const float k1 = 1.0f / 13.0f;
    const float k5 = 5.0f / 13.0f;
    float* ob = out + (size_t)plane * HW + tr * TILE_R * W_;

    for (int idx = threadIdx.x; idx < TILE_R * W_ / 4; idx += 256) {
        const int o = idx / 56;               // local output row 0..15
        const int q = idx - o * 56;
        const int c4 = q * 4;

        const float* r0 = tile + o * W_ + c4;
        const float* r1 = r0 + W_;
        const float* r2 = r1 + W_;

        float4 t0 = *(const float4*)r0;
        float4 t1 = *(const float4*)r1;
        float4 t2 = *(const float4*)r2;

        float yv0[6] = {0.f, t0.x, t0.y, t0.z, t0.w, 0.f};
        float yv1[6] = {0.f, t1.x, t1.y, t1.z, t1.w, 0.f};
        float yv2[6] = {0.f, t2.x, t2.y, t2.z, t2.w, 0.f};
        if (c4 > 0)        { yv0[0] = r0[-1]; yv1[0] = r1[-1]; yv2[0] = r2[-1]; }
        if (c4 + 4 < W_)   { yv0[5] = r0[4];  yv1[5] = r1[4];  yv2[5] = r2[4]; }

        float4 ov;
        float* op = (float*)&ov;
#pragma unroll
        for (int j = 0; j < 4; j++) {
            const float cen = yv1[j + 1];
            const float ring = yv0[j] + yv0[j + 1] + yv0[j + 2]
                             + yv1[j]              + yv1[j + 2]
                             + yv2[j] + yv2[j + 1] + yv2[j + 2];
            const float blur = ring * k1 + cen * k5;
            const float y1 = 0.64f * cen + 0.36f * blur;
            const float y2 = (0.64f * y1 + 0.36f * gm) * 0.64f;
            const float z = (y2 < 0.3f) ? y2 : 1.0f - y2;
            op[j] = (z - m) / sd;
        }
        *(float4*)(ob + o * W_ + c4) = ov;
    }
}

extern "C" void kernel_launch(void* const* d_in, const int* in_sizes, int n_in,
                              void* d_out, int out_size) {
    const float* x    = (const float*)d_in[0];
    const float* mean = (const float*)d_in[1];
    const float* stdv = (const float*)d_in[2];
    float* out = (float*)d_out;

    const int B = in_sizes[0] / (3 * HW);

    reduce_kernel<<<B * SEGS, 256>>>(x, stdv);
    main_kernel<<<B * 3 * (H_ / TILE_R), 256>>>(x, mean, stdv, out);
}

// round 3
// speedup vs baseline: 1.3694x; 1.2210x over previous
#include <cuda_runtime.h>

#define HW 50176
#define W_ 224
#define H_ 224
#define SEGS 8
#define SEG_ROWS 28          // 224 / 8
#define QPR 56               // quads per row (224/4)
#define RG  56               // row groups per plane (224/4)

// Per-image partial weighted gray sums: g_part[b*SEGS + s]
__device__ float g_part[1024 * SEGS];

// ---------------------------------------------------------------------------
// Kernel 1: balanced partial reduction. FROZEN (bitwise) from R2 — gm's fp
// value determines solarize-threshold flips; do not perturb.
// ---------------------------------------------------------------------------
__global__ void __launch_bounds__(256)
reduce_kernel(const float* __restrict__ x,
              const float* __restrict__ stdv) {
    const int b = blockIdx.x >> 3;
    const int s = blockIdx.x & 7;
    const float* p = x + (size_t)b * 3 * HW + s * SEG_ROWS * W_;

    const float gw0 = 0.299f * stdv[0];
    const float gw1 = 0.587f * stdv[1];
    const float gw2 = 0.114f * stdv[2];

    float acc = 0.f;
    for (int i = threadIdx.x; i < SEG_ROWS * W_ / 4; i += 256) {
        const int pix = i * 4;
        const int lr = pix / W_;
        const int c0 = pix - lr * W_;
        const int gr = s * SEG_ROWS + lr;
        float4 a0 = *(const float4*)(p + pix);
        float4 a1 = *(const float4*)(p + HW + pix);
        float4 a2 = *(const float4*)(p + 2 * HW + pix);
        const float ny = (gr == 0 || gr == H_ - 1) ? 2.f : 3.f;

        float e0[4] = {a0.x, a0.y, a0.z, a0.w};
        float e1[4] = {a1.x, a1.y, a1.z, a1.w};
        float e2[4] = {a2.x, a2.y, a2.z, a2.w};
#pragma unroll
        for (int j = 0; j < 4; j++) {
            const int c = c0 + j;
            const float nx = (c == 0 || c == W_ - 1) ? 2.f : 3.f;
            const float coef = 0.64f + 0.36f * (ny * nx + 4.f) * (1.f / 13.f);
            const float gx = gw0 * e0[j] + gw1 * e1[j] + gw2 * e2[j];
            acc += coef * gx;
        }
    }

    __shared__ float red[8];
#pragma unroll
    for (int off = 16; off > 0; off >>= 1)
        acc += __shfl_down_sync(0xffffffffu, acc, off);
    const int lane = threadIdx.x & 31;
    const int warp = threadIdx.x >> 5;
    if (lane == 0) red[warp] = acc;
    __syncthreads();
    if (threadIdx.x == 0) {
        float t = 0.f;
#pragma unroll
        for (int w = 0; w < 8; w++) t += red[w];
        g_part[blockIdx.x] = t;
    }
}

// ---------------------------------------------------------------------------
// Kernel 2: register/shuffle fused pipeline. Thread = one column-quad x 4
// output rows. 6 aligned LDG.128, horizontal halos by warp shuffle,
// predicated scalar LDG only at warp edges, 4 STG.128. No smem, no barriers.
// Per-pixel fp math identical to R2.
// ---------------------------------------------------------------------------
__global__ void __launch_bounds__(256)
main_kernel(const float* __restrict__ x,
            const float* __restrict__ mean,
            const float* __restrict__ stdv,
            float* __restrict__ out,
            int nplanes) {
    const int idx = blockIdx.x * 256 + threadIdx.x;
    const int q = idx % QPR;                  // column quad 0..55
    const int t2 = idx / QPR;
    const int rg = t2 % RG;                   // row group 0..55
    const int plane = t2 / RG;
    if (plane >= nplanes) return;

    const int b = plane / 3;
    const int ch = plane - b * 3;
    const float m = mean[ch];
    const float sd = stdv[ch];

    // gm from frozen partials (same summation as R2)
    float gm;
    {
        float ps = 0.f;
#pragma unroll
        for (int i = 0; i < SEGS; i++) ps += g_part[b * SEGS + i];
        const double SC = 0.64 * (double)HW + 0.36 * (448900.0 + 4.0 * HW) / 13.0;
        const float cm = 0.299f * mean[0] + 0.587f * mean[1] + 0.114f * mean[2];
        gm = (ps + cm * (float)SC) * (1.0f / (float)HW);
    }

    const float* p = x + (size_t)plane * HW;
    const int c4 = q * 4;
    const int r0 = rg * 4;

    // ---- 6 source rows (r0-1 .. r0+4), affine applied, zero y-pad OOB ----
    float4 v[6];
#pragma unroll
    for (int k = 0; k < 6; k++) {
        const int row = r0 - 1 + k;
        if (row >= 0 && row < H_) {
            float4 u = *(const float4*)(p + row * W_ + c4);
            v[k].x = fmaf(u.x, sd, m);
            v[k].y = fmaf(u.y, sd, m);
            v[k].z = fmaf(u.z, sd, m);
            v[k].w = fmaf(u.w, sd, m);
        } else {
            v[k] = make_float4(0.f, 0.f, 0.f, 0.f);
        }
    }

    // ---- horizontal halos: shuffle interior, scalar LDG at warp/image edge ----
    const unsigned lane = threadIdx.x & 31;
    float L[6], R[6];
#pragma unroll
    for (int k = 0; k < 6; k++) {
        L[k] = __shfl_up_sync(0xffffffffu, v[k].w, 1);
        R[k] = __shfl_down_sync(0xffffffffu, v[k].x, 1);
    }
    if (q == 0) {
#pragma unroll
        for (int k = 0; k < 6; k++) L[k] = 0.f;
    } else if (lane == 0) {
#pragma unroll
        for (int k = 0; k < 6; k++) {
            const int row = r0 - 1 + k;
            L[k] = (row >= 0 && row < H_) ? fmaf(p[row * W_ + c4 - 1], sd, m) : 0.f;
        }
    }
    if (q == QPR - 1) {
#pragma unroll
        for (int k = 0; k < 6; k++) R[k] = 0.f;
    } else if (lane == 31) {
#pragma unroll
        for (int k = 0; k < 6; k++) {
            const int row = r0 - 1 + k;
            R[k] = (row >= 0 && row < H_) ? fmaf(p[row * W_ + c4 + 4], sd, m) : 0.f;
        }
    }

    // ---- 4 output rows ----
    const float k1 = 1.0f / 13.0f;
    const float k5 = 5.0f / 13.0f;
    float* ob = out + (size_t)plane * HW + r0 * W_ + c4;

#pragma unroll
    for (int o = 0; o < 4; o++) {
        const float yt[6] = {L[o],     v[o].x,   v[o].y,   v[o].z,   v[o].w,   R[o]};
        const float ym[6] = {L[o + 1], v[o + 1].x, v[o + 1].y, v[o + 1].z, v[o + 1].w, R[o + 1]};
        const float yb[6] = {L[o + 2], v[o + 2].x, v[o + 2].y, v[o + 2].z, v[o + 2].w, R[o + 2]};

        float4 ov;
        float* op = (float*)&ov;
#pragma unroll
        for (int j = 0; j < 4; j++) {
            const float cen = ym[j + 1];
            const float ring = yt[j] + yt[j + 1] + yt[j + 2]
                             + ym[j]             + ym[j + 2]
                             + yb[j] + yb[j + 1] + yb[j + 2];
            const float blur = ring * k1 + cen * k5;
            const float y1 = 0.64f * cen + 0.36f * blur;
            const float y2 = (0.64f * y1 + 0.36f * gm) * 0.64f;
            const float z = (y2 < 0.3f) ? y2 : 1.0f - y2;
            op[j] = (z - m) / sd;
        }
        *(float4*)(ob + o * W_) = ov;
    }
}

extern "C" void kernel_launch(void* const* d_in, const int* in_sizes, int n_in,
                              void* d_out, int out_size) {
    const float* x    = (const float*)d_in[0];
    const float* mean = (const float*)d_in[1];
    const float* stdv = (const float*)d_in[2];
    float* out = (float*)d_out;

    const int B = in_sizes[0] / (3 * HW);
    const int nplanes = B * 3;

    reduce_kernel<<<B * SEGS, 256>>>(x, stdv);

    const int total = nplanes * RG * QPR;     // one thread per (quad, rowgroup)
    main_kernel<<<(total + 255) / 256, 256>>>(x, mean, stdv, out, nplanes);
}